// round 3
// baseline (speedup 1.0000x reference)
#include <cuda_runtime.h>
#include <cuda_bf16.h>
#include <cstdint>

#define B_ 128
#define G_ 512
#define H_ 128

static __device__ __constant__ float kAlphaHalf = 0.05f;   // ALPHA * 0.5

// ---------------- scratch (static device globals; no allocation) -------------
__device__ float          g_buf[B_ * H_];        // g (B,H) fp32
__device__ __nv_bfloat16  xbf_buf[B_ * G_];      // baseline in bf16 (B,G)
__device__ float          corr_buf[G_ * B_];     // Sum_h g*S, layout [i][b]
__device__ float          bx_buf[B_ * G_];       // Sum_j b2[jG+i] x[b,j], layout [b][i]

// ============================================================================
// K1: encoders -> g, plus bf16 copy of baseline. One CTA per sample b.
// ============================================================================
__global__ __launch_bounds__(128) void k1_encode(
    const int*   __restrict__ pert,
    const float* __restrict__ x,
    const float* __restrict__ embW,
    const float* __restrict__ geW1, const float* __restrict__ geb1,
    const float* __restrict__ geW2, const float* __restrict__ geb2,
    const float* __restrict__ grnW1, const float* __restrict__ grnb1)
{
    __shared__ float sx[G_];
    __shared__ float sh[H_];
    __shared__ float sc[2 * H_];
    const int b = blockIdx.x, t = threadIdx.x;
    const float* xr = x + b * G_;

    #pragma unroll
    for (int q = 0; q < 4; q++) {
        float v = xr[q * 128 + t];
        sx[q * 128 + t] = v;
        xbf_buf[b * G_ + q * 128 + t] = __float2bfloat16(v);
    }
    __syncthreads();

    // h = relu(x @ ge_W1^T + b1)
    float acc = geb1[t];
    {
        const float* w = geW1 + t * G_;
        #pragma unroll 8
        for (int j = 0; j < G_; j++) acc += w[j] * sx[j];
    }
    sh[t] = fmaxf(acc, 0.f);
    __syncthreads();

    // gene_emb = relu(h @ ge_W2^T + b2)
    acc = geb2[t];
    {
        const float* w = geW2 + t * H_;
        #pragma unroll 8
        for (int j = 0; j < H_; j++) acc += w[j] * sh[j];
    }
    sc[H_ + t] = fmaxf(acc, 0.f);
    sc[t] = embW[pert[b] * H_ + t];
    __syncthreads();

    // g = relu(combined @ grn_W1^T + b1)
    acc = grnb1[t];
    {
        const float* w = grnW1 + t * (2 * H_);
        #pragma unroll 8
        for (int j = 0; j < 2 * H_; j++) acc += w[j] * sc[j];
    }
    g_buf[b * H_ + t] = fmaxf(acc, 0.f);
}

// ============================================================================
// K2: Bx[b,i] = Sum_j grn_b2[j*G+i] * x[b,j]   (grn_b2 is zero in practice,
// but computed for correctness). Grid 64: (4 b-chunks of 32) x (16 i-chunks of 32).
// ============================================================================
__global__ __launch_bounds__(256) void k2_bx(
    const float* __restrict__ x, const float* __restrict__ b2)
{
    const int bc = blockIdx.x >> 4, ic = blockIdx.x & 15;
    const int t = threadIdx.x;
    const int i = ic * 32 + (t & 31);
    const int bg = t >> 5;                 // warp id 0..7 -> 4 b rows each
    const float* xr = x + (bc * 32 + bg * 4) * G_;
    float a0 = 0.f, a1 = 0.f, a2 = 0.f, a3 = 0.f;
    for (int j = 0; j < G_; j++) {
        float bv = __ldg(&b2[j * G_ + i]);
        a0 += bv * __ldg(xr + 0 * G_ + j);
        a1 += bv * __ldg(xr + 1 * G_ + j);
        a2 += bv * __ldg(xr + 2 * G_ + j);
        a3 += bv * __ldg(xr + 3 * G_ + j);
    }
    float* o = bx_buf + (bc * 32 + bg * 4) * G_ + i;
    o[0 * G_] = a0; o[1 * G_] = a1; o[2 * G_] = a2; o[3 * G_] = a3;
}

// ============================================================================
// K3: the big one. One CTA per output gene index i (512 CTAs).
//   C[b,h] = Sum_j X[b,j] * W2[(j*G + i)*H + h]     (GEMM 128x128x512, bf16 mma)
//   corr[i,b] = Sum_h C[b,h] * g[b,h]               (fused epilogue)
// HBM traffic: grn_W2 read exactly once (134 MB).
// ============================================================================
__device__ __forceinline__ void ldsm_x4(uint32_t addr, uint32_t& r0, uint32_t& r1,
                                        uint32_t& r2, uint32_t& r3) {
    asm volatile("ldmatrix.sync.aligned.m8n8.x4.shared.b16 {%0,%1,%2,%3},[%4];"
                 : "=r"(r0), "=r"(r1), "=r"(r2), "=r"(r3) : "r"(addr));
}
__device__ __forceinline__ void ldsm_x4_t(uint32_t addr, uint32_t& r0, uint32_t& r1,
                                          uint32_t& r2, uint32_t& r3) {
    asm volatile("ldmatrix.sync.aligned.m8n8.x4.trans.shared.b16 {%0,%1,%2,%3},[%4];"
                 : "=r"(r0), "=r"(r1), "=r"(r2), "=r"(r3) : "r"(addr));
}
#define MMA16816(d, a, b0r, b1r)                                            \
    asm volatile(                                                           \
        "mma.sync.aligned.m16n8k16.row.col.f32.bf16.bf16.f32 "              \
        "{%0,%1,%2,%3},{%4,%5,%6,%7},{%8,%9},{%0,%1,%2,%3};"                \
        : "+f"((d)[0]), "+f"((d)[1]), "+f"((d)[2]), "+f"((d)[3])            \
        : "r"((a)[0]), "r"((a)[1]), "r"((a)[2]), "r"((a)[3]),               \
          "r"(b0r), "r"(b1r))

__global__ __launch_bounds__(256, 2) void k3_main(const float* __restrict__ W2)
{
    constexpr int PA = 72;    // A smem pitch (bf16 elems): 144B -> stride 4 banks
    constexpr int PB = 136;   // B smem pitch: 272B -> stride 4 banks
    __shared__ __nv_bfloat16 sA[128 * PA];   // X chunk: 128 b x 64 j
    __shared__ __nv_bfloat16 sB[64 * PB];    // W chunk: 64 j x 128 h
    __shared__ float pred[128][8];

    const int i_cta = blockIdx.x;
    const int t = threadIdx.x;
    const int lane = t & 31, w = t >> 5;
    const int wm = w & 3;     // b quadrant (32 rows)
    const int wn = w >> 2;    // h half (64 cols)

    float acc[2][8][4];
    #pragma unroll
    for (int mt = 0; mt < 2; mt++)
        #pragma unroll
        for (int nt = 0; nt < 8; nt++)
            #pragma unroll
            for (int r = 0; r < 4; r++) acc[mt][nt][r] = 0.f;

    for (int c = 0; c < 8; c++) {
        const int j0 = c * 64;
        // --- stage X chunk (bf16, from L2-resident xbf_buf) ---
        for (int idx = t; idx < 128 * 8; idx += 256) {
            const int r = idx >> 3, q = idx & 7;
            uint4 v = *reinterpret_cast<const uint4*>(&xbf_buf[r * G_ + j0 + q * 8]);
            *reinterpret_cast<uint4*>(&sA[r * PA + q * 8]) = v;
        }
        // --- stage W chunk: 64 rows x 128 fp32 -> bf16 (the HBM stream) ---
        for (int idx = t; idx < 64 * 16; idx += 256) {
            const int r = idx >> 4, q = idx & 15;
            const float* gp = W2 + (((j0 + r) * G_ + i_cta) * H_ + q * 8);
            float4 v0 = *reinterpret_cast<const float4*>(gp);
            float4 v1 = *reinterpret_cast<const float4*>(gp + 4);
            __nv_bfloat162 p0 = __floats2bfloat162_rn(v0.x, v0.y);
            __nv_bfloat162 p1 = __floats2bfloat162_rn(v0.z, v0.w);
            __nv_bfloat162 p2 = __floats2bfloat162_rn(v1.x, v1.y);
            __nv_bfloat162 p3 = __floats2bfloat162_rn(v1.z, v1.w);
            uint4 o;
            o.x = *reinterpret_cast<uint32_t*>(&p0);
            o.y = *reinterpret_cast<uint32_t*>(&p1);
            o.z = *reinterpret_cast<uint32_t*>(&p2);
            o.w = *reinterpret_cast<uint32_t*>(&p3);
            *reinterpret_cast<uint4*>(&sB[r * PB + q * 8]) = o;
        }
        __syncthreads();

        #pragma unroll
        for (int ks = 0; ks < 64; ks += 16) {
            uint32_t afr[2][4];
            #pragma unroll
            for (int mt = 0; mt < 2; mt++) {
                const int row = wm * 32 + mt * 16 + (lane & 15);
                const int col = ks + ((lane >> 4) << 3);
                uint32_t a = (uint32_t)__cvta_generic_to_shared(&sA[row * PA + col]);
                ldsm_x4(a, afr[mt][0], afr[mt][1], afr[mt][2], afr[mt][3]);
            }
            uint32_t bfr[4][4];
            #pragma unroll
            for (int n4 = 0; n4 < 4; n4++) {
                const int krow = ks + (lane & 15);
                const int col = wn * 64 + n4 * 16 + ((lane >> 4) << 3);
                uint32_t a = (uint32_t)__cvta_generic_to_shared(&sB[krow * PB + col]);
                ldsm_x4_t(a, bfr[n4][0], bfr[n4][1], bfr[n4][2], bfr[n4][3]);
            }
            #pragma unroll
            for (int mt = 0; mt < 2; mt++)
                #pragma unroll
                for (int nt = 0; nt < 8; nt++) {
                    const int n4 = nt >> 1, p = (nt & 1) * 2;
                    MMA16816(acc[mt][nt], afr[mt], bfr[n4][p], bfr[n4][p + 1]);
                }
        }
        __syncthreads();
    }

    // --- epilogue: corr[i,b] = Sum_h C[b,h]*g[b,h] (deterministic reduction) ---
    const int rg = lane >> 2, tig = lane & 3;
    #pragma unroll
    for (int mt = 0; mt < 2; mt++) {
        float p0 = 0.f, p1 = 0.f;
        const int brow = wm * 32 + mt * 16 + rg;
        #pragma unroll
        for (int nt = 0; nt < 8; nt++) {
            const int h0 = wn * 64 + nt * 8 + tig * 2;
            float g0 = __ldg(&g_buf[brow * H_ + h0]);
            float g1 = __ldg(&g_buf[brow * H_ + h0 + 1]);
            float g2 = __ldg(&g_buf[(brow + 8) * H_ + h0]);
            float g3 = __ldg(&g_buf[(brow + 8) * H_ + h0 + 1]);
            p0 += acc[mt][nt][0] * g0 + acc[mt][nt][1] * g1;
            p1 += acc[mt][nt][2] * g2 + acc[mt][nt][3] * g3;
        }
        pred[brow][wn * 4 + tig]     = p0;
        pred[brow + 8][wn * 4 + tig] = p1;
    }
    __syncthreads();
    if (t < 128) {
        float s = 0.f;
        #pragma unroll
        for (int cc = 0; cc < 8; cc++) s += pred[t][cc];
        corr_buf[i_cta * B_ + t] = s;
    }
}

// ============================================================================
// K4: y = x/c + (alpha/2)*(corr + Bx)/c^2 ; decoder ; residual. CTA per b.
// ============================================================================
__global__ __launch_bounds__(128) void k4_dec(
    const float* __restrict__ x,
    const float* __restrict__ dW1, const float* __restrict__ db1,
    const float* __restrict__ dW2, const float* __restrict__ db2,
    float* __restrict__ out)
{
    __shared__ float sx[G_], sy[G_], sd[H_];
    const int b = blockIdx.x, t = threadIdx.x;
    const float cinv = 1.0f / (1.0f + 1e-6f);
    const float scale = kAlphaHalf * cinv * cinv;

    #pragma unroll
    for (int q = 0; q < 4; q++) {
        const int i = q * 128 + t;
        const float xv = x[b * G_ + i];
        sx[i] = xv;
        const float corr = corr_buf[i * B_ + b] + bx_buf[b * G_ + i];
        sy[i] = xv * cinv + corr * scale;
    }
    __syncthreads();

    float acc = db1[t];
    {
        const float* wp = dW1 + t * G_;
        #pragma unroll 8
        for (int j = 0; j < G_; j++) acc += wp[j] * sy[j];
    }
    sd[t] = fmaxf(acc, 0.f);
    __syncthreads();

    #pragma unroll
    for (int q = 0; q < 4; q++) {
        const int i = q * 128 + t;
        float a2 = db2[i];
        const float* w2 = dW2 + i * H_;
        #pragma unroll 8
        for (int h = 0; h < H_; h++) a2 += w2[h] * sd[h];
        out[b * G_ + i] = sx[i] + a2;
    }
}

// ============================================================================
extern "C" void kernel_launch(void* const* d_in, const int* in_sizes, int n_in,
                              void* d_out, int out_size)
{
    (void)in_sizes; (void)n_in; (void)out_size;
    const int*   pert  = (const int*)  d_in[0];
    const float* x     = (const float*)d_in[1];
    const float* embW  = (const float*)d_in[2];
    const float* geW1  = (const float*)d_in[3];
    const float* geb1  = (const float*)d_in[4];
    const float* geW2  = (const float*)d_in[5];
    const float* geb2  = (const float*)d_in[6];
    const float* grnW1 = (const float*)d_in[7];
    const float* grnb1 = (const float*)d_in[8];
    const float* grnW2 = (const float*)d_in[9];
    const float* grnb2 = (const float*)d_in[10];
    const float* dW1   = (const float*)d_in[11];
    const float* db1   = (const float*)d_in[12];
    const float* dW2   = (const float*)d_in[13];
    const float* db2   = (const float*)d_in[14];
    float* out = (float*)d_out;

    k1_encode<<<B_, 128>>>(pert, x, embW, geW1, geb1, geW2, geb2, grnW1, grnb1);
    k2_bx<<<64, 256>>>(x, grnb2);
    k3_main<<<G_, 256>>>(grnW2);
    k4_dec<<<B_, 128>>>(x, dW1, db1, dW2, db2, out);
}

// round 5
// speedup vs baseline: 2.4692x; 2.4692x over previous
#include <cuda_runtime.h>
#include <cuda_bf16.h>
#include <cstdint>

#define B_ 128
#define G_ 512
#define H_ 128

static __device__ __constant__ float kAlphaHalf = 0.05f;   // ALPHA * 0.5

// ---------------- scratch (static device globals; no allocation) -------------
__device__ float          g_buf[B_ * H_];        // g (B,H) fp32
__device__ __nv_bfloat16  xbf_buf[B_ * G_];      // baseline in bf16 (B,G)
__device__ float          corr_buf[B_ * G_];     // Sum_h g*S, layout [b][i]
__device__ float          bx_buf[B_ * G_];       // Sum_j b2[jG+i] x[b,j], [b][i]

__device__ __forceinline__ float wred(float v) {
    v += __shfl_xor_sync(0xffffffffu, v, 16);
    v += __shfl_xor_sync(0xffffffffu, v, 8);
    v += __shfl_xor_sync(0xffffffffu, v, 4);
    v += __shfl_xor_sync(0xffffffffu, v, 2);
    v += __shfl_xor_sync(0xffffffffu, v, 1);
    return v;
}
__device__ __forceinline__ float dot4(float4 a, float4 b) {
    return a.x * b.x + a.y * b.y + a.z * b.z + a.w * b.w;
}

// ============================================================================
// K1: encoders -> g, plus bf16 copy of baseline. One CTA per sample b.
// Warp-per-output, coalesced float4 weight reads, shuffle reduce.
// ============================================================================
__global__ __launch_bounds__(256) void k1_encode(
    const int*   __restrict__ pert,
    const float* __restrict__ x,
    const float* __restrict__ embW,
    const float* __restrict__ geW1, const float* __restrict__ geb1,
    const float* __restrict__ geW2, const float* __restrict__ geb2,
    const float* __restrict__ grnW1, const float* __restrict__ grnb1)
{
    __shared__ float sx[G_];
    __shared__ float sh[H_];
    __shared__ float sc[2 * H_];
    const int b = blockIdx.x, t = threadIdx.x;
    const int lane = t & 31, w = t >> 5;
    const float* xr = x + b * G_;

    #pragma unroll
    for (int q = 0; q < 2; q++) {
        const int i = q * 256 + t;
        float v = xr[i];
        sx[i] = v;
        xbf_buf[b * G_ + i] = __float2bfloat16(v);
    }
    if (t < 128) sc[t] = embW[pert[b] * H_ + t];
    __syncthreads();

    const float4* sx4 = (const float4*)sx;
    // h = relu(x @ geW1^T + b1): 128 outputs, 8 warps, 16 each
    #pragma unroll 4
    for (int o = 0; o < 16; o++) {
        const int h = w * 16 + o;
        const float4* wp = (const float4*)(geW1 + h * G_);
        float acc = 0.f;
        #pragma unroll
        for (int k = 0; k < 4; k++) acc += dot4(wp[lane + 32 * k], sx4[lane + 32 * k]);
        acc = wred(acc);
        if (lane == 0) sh[h] = fmaxf(acc + geb1[h], 0.f);
    }
    __syncthreads();

    const float4* sh4 = (const float4*)sh;
    #pragma unroll 4
    for (int o = 0; o < 16; o++) {
        const int h = w * 16 + o;
        const float4* wp = (const float4*)(geW2 + h * H_);
        float acc = dot4(wp[lane], sh4[lane]);
        acc = wred(acc);
        if (lane == 0) sc[H_ + h] = fmaxf(acc + geb2[h], 0.f);
    }
    __syncthreads();

    const float4* sc4 = (const float4*)sc;
    #pragma unroll 4
    for (int o = 0; o < 16; o++) {
        const int h = w * 16 + o;
        const float4* wp = (const float4*)(grnW1 + h * 2 * H_);
        float acc = dot4(wp[lane], sc4[lane]) + dot4(wp[lane + 32], sc4[lane + 32]);
        acc = wred(acc);
        if (lane == 0) g_buf[b * H_ + h] = fmaxf(acc + grnb1[h], 0.f);
    }
}

// ============================================================================
// K2: Bx = X(128x512) @ B2(512x512) (B2 = grn_b2 viewed [j][i]).
// Tiled fp32 GEMM: 64 CTAs (8 b-tiles of 16 x 8 i-tiles of 64).
// ============================================================================
__global__ __launch_bounds__(256) void k2_bx(
    const float* __restrict__ x, const float* __restrict__ b2)
{
    __shared__ float sX[16][G_];      // 32 KB
    __shared__ float sB2[32][64];     // 8 KB
    const int bc = blockIdx.x >> 3, ic = blockIdx.x & 7;
    const int b0 = bc * 16, i0 = ic * 64;
    const int t = threadIdx.x;
    const int i_loc = t & 63, bgrp = t >> 6;   // bgrp uniform per warp

    // stage X tile [16 x 512]
    for (int idx = t; idx < 16 * 128; idx += 256) {
        const int r = idx >> 7, c4 = idx & 127;
        ((float4*)sX[r])[c4] = *(const float4*)(x + (b0 + r) * G_ + c4 * 4);
    }

    float acc[4] = {0.f, 0.f, 0.f, 0.f};
    for (int jc = 0; jc < 16; jc++) {
        __syncthreads();
        for (int idx = t; idx < 32 * 16; idx += 256) {
            const int r = idx >> 4, q = idx & 15;
            ((float4*)sB2[r])[q] = *(const float4*)(b2 + (jc * 32 + r) * G_ + i0 + q * 4);
        }
        __syncthreads();
        #pragma unroll 8
        for (int j = 0; j < 32; j++) {
            const float bv = sB2[j][i_loc];
            #pragma unroll
            for (int r = 0; r < 4; r++)
                acc[r] += bv * sX[bgrp * 4 + r][jc * 32 + j];
        }
    }
    #pragma unroll
    for (int r = 0; r < 4; r++)
        bx_buf[(b0 + bgrp * 4 + r) * G_ + i0 + i_loc] = acc[r];
}

// ============================================================================
// K3: C[b,h] = Sum_j X[b,j] * W2[(j*G+i)*H+h]  (128x128x512 bf16 mma)
//     corr[b,i] = Sum_h C[b,h] * g[b,h]        (fused epilogue)
// cp.async double-buffered: W2 chunk (fp32) + X chunk (bf16) staged for c+1
// while chunk c is converted + MMA'd. HBM: W2 read exactly once (134 MB).
// ============================================================================
__device__ __forceinline__ void ldsm_x4(uint32_t addr, uint32_t& r0, uint32_t& r1,
                                        uint32_t& r2, uint32_t& r3) {
    asm volatile("ldmatrix.sync.aligned.m8n8.x4.shared.b16 {%0,%1,%2,%3},[%4];"
                 : "=r"(r0), "=r"(r1), "=r"(r2), "=r"(r3) : "r"(addr));
}
__device__ __forceinline__ void ldsm_x4_t(uint32_t addr, uint32_t& r0, uint32_t& r1,
                                          uint32_t& r2, uint32_t& r3) {
    asm volatile("ldmatrix.sync.aligned.m8n8.x4.trans.shared.b16 {%0,%1,%2,%3},[%4];"
                 : "=r"(r0), "=r"(r1), "=r"(r2), "=r"(r3) : "r"(addr));
}
__device__ __forceinline__ void cp16(void* dst, const void* src) {
    uint32_t d = (uint32_t)__cvta_generic_to_shared(dst);
    asm volatile("cp.async.cg.shared.global [%0],[%1],16;\n" :: "r"(d), "l"(src));
}
#define MMA16816(d, a, b0r, b1r)                                            \
    asm volatile(                                                           \
        "mma.sync.aligned.m16n8k16.row.col.f32.bf16.bf16.f32 "              \
        "{%0,%1,%2,%3},{%4,%5,%6,%7},{%8,%9},{%0,%1,%2,%3};"                \
        : "+f"((d)[0]), "+f"((d)[1]), "+f"((d)[2]), "+f"((d)[3])            \
        : "r"((a)[0]), "r"((a)[1]), "r"((a)[2]), "r"((a)[3]),               \
          "r"(b0r), "r"(b1r))

#define K3_CH   32
#define K3_NCH  16
#define K3_PA   40
#define K3_PB   136
// dynamic smem layout (bytes)
#define K3_SA_OFF   0                                  // 2 * 128*40*2 = 20480
#define K3_SW_OFF   20480                              // 2 * 32*128*4 = 32768
#define K3_SB_OFF   (20480 + 32768)                    // 32*136*2     = 8704
#define K3_PRED_OFF (20480 + 32768 + 8704)             // 128*8*4      = 4096
#define K3_SMEM     (K3_PRED_OFF + 4096)               // 66048

__global__ __launch_bounds__(256, 2) void k3_main(const float* __restrict__ W2)
{
    extern __shared__ char smem[];
    __nv_bfloat16* sA   = (__nv_bfloat16*)(smem + K3_SA_OFF);  // [2][128*PA]
    float*         sW   = (float*)(smem + K3_SW_OFF);          // [2][32*128]
    __nv_bfloat16* sB   = (__nv_bfloat16*)(smem + K3_SB_OFF);  // [32*PB]
    float (*pred)[8]    = (float (*)[8])(smem + K3_PRED_OFF);  // [128][8]

    const int i_cta = blockIdx.x;
    const int t = threadIdx.x;
    const int lane = t & 31, w = t >> 5;
    const int wm = w & 3, wn = w >> 2;

    float acc[2][8][4];
    #pragma unroll
    for (int mt = 0; mt < 2; mt++)
        #pragma unroll
        for (int nt = 0; nt < 8; nt++)
            #pragma unroll
            for (int r = 0; r < 4; r++) acc[mt][nt][r] = 0.f;

    auto issue = [&](int c) {
        const int buf = c & 1;
        const int j0 = c * K3_CH;
        // X chunk: 128 rows x 32 bf16 (64B = 4x16B)
        #pragma unroll
        for (int k = 0; k < 2; k++) {
            const int idx = t + k * 256;
            const int r = idx >> 2, q = idx & 3;
            cp16(&sA[buf * 128 * K3_PA + r * K3_PA + q * 8],
                 &xbf_buf[r * G_ + j0 + q * 8]);
        }
        // W chunk: 32 rows x 128 fp32 (512B = 32x16B)
        #pragma unroll
        for (int k = 0; k < 4; k++) {
            const int idx = t + k * 256;
            const int r = idx >> 5, q = idx & 31;
            cp16(&sW[buf * K3_CH * H_ + r * H_ + q * 4],
                 W2 + ((long)(j0 + r) * G_ + i_cta) * H_ + q * 4);
        }
        asm volatile("cp.async.commit_group;\n" ::: "memory");
    };

    issue(0);
    for (int c = 0; c < K3_NCH; c++) {
        __syncthreads();                      // prev mma done: bufs (c+1)&1, sB free
        if (c + 1 < K3_NCH) {
            issue(c + 1);
            asm volatile("cp.async.wait_group 1;\n" ::: "memory");
        } else {
            asm volatile("cp.async.wait_group 0;\n" ::: "memory");
        }
        __syncthreads();                      // chunk c visible to all

        // convert sW[c&1] -> sB (bf16). 16 floats per thread.
        {
            const float* wsrc = sW + (c & 1) * K3_CH * H_;
            const int r = t >> 3, c0 = (t & 7) * 16;
            const float4* src = (const float4*)(wsrc + r * H_ + c0);
            float4 v0 = src[0], v1 = src[1], v2 = src[2], v3 = src[3];
            __nv_bfloat162 p0 = __floats2bfloat162_rn(v0.x, v0.y);
            __nv_bfloat162 p1 = __floats2bfloat162_rn(v0.z, v0.w);
            __nv_bfloat162 p2 = __floats2bfloat162_rn(v1.x, v1.y);
            __nv_bfloat162 p3 = __floats2bfloat162_rn(v1.z, v1.w);
            __nv_bfloat162 p4 = __floats2bfloat162_rn(v2.x, v2.y);
            __nv_bfloat162 p5 = __floats2bfloat162_rn(v2.z, v2.w);
            __nv_bfloat162 p6 = __floats2bfloat162_rn(v3.x, v3.y);
            __nv_bfloat162 p7 = __floats2bfloat162_rn(v3.z, v3.w);
            uint4 o0, o1;
            o0.x = *(uint32_t*)&p0; o0.y = *(uint32_t*)&p1;
            o0.z = *(uint32_t*)&p2; o0.w = *(uint32_t*)&p3;
            o1.x = *(uint32_t*)&p4; o1.y = *(uint32_t*)&p5;
            o1.z = *(uint32_t*)&p6; o1.w = *(uint32_t*)&p7;
            *(uint4*)&sB[r * K3_PB + c0]     = o0;
            *(uint4*)&sB[r * K3_PB + c0 + 8] = o1;
        }
        __syncthreads();

        const __nv_bfloat16* sAc = sA + (c & 1) * 128 * K3_PA;
        #pragma unroll
        for (int ks = 0; ks < K3_CH; ks += 16) {
            uint32_t afr[2][4];
            #pragma unroll
            for (int mt = 0; mt < 2; mt++) {
                const int row = wm * 32 + mt * 16 + (lane & 15);
                const int col = ks + ((lane >> 4) << 3);
                uint32_t a = (uint32_t)__cvta_generic_to_shared(&sAc[row * K3_PA + col]);
                ldsm_x4(a, afr[mt][0], afr[mt][1], afr[mt][2], afr[mt][3]);
            }
            uint32_t bfr[4][4];
            #pragma unroll
            for (int n4 = 0; n4 < 4; n4++) {
                const int krow = ks + (lane & 15);
                const int col = wn * 64 + n4 * 16 + ((lane >> 4) << 3);
                uint32_t a = (uint32_t)__cvta_generic_to_shared(&sB[krow * K3_PB + col]);
                ldsm_x4_t(a, bfr[n4][0], bfr[n4][1], bfr[n4][2], bfr[n4][3]);
            }
            #pragma unroll
            for (int mt = 0; mt < 2; mt++)
                #pragma unroll
                for (int nt = 0; nt < 8; nt++) {
                    const int n4 = nt >> 1, p = (nt & 1) * 2;
                    MMA16816(acc[mt][nt], afr[mt], bfr[n4][p], bfr[n4][p + 1]);
                }
        }
    }

    // epilogue: corr[b,i_cta] = Sum_h C[b,h]*g[b,h] (deterministic)
    const int rg = lane >> 2, tig = lane & 3;
    #pragma unroll
    for (int mt = 0; mt < 2; mt++) {
        float p0 = 0.f, p1 = 0.f;
        const int brow = wm * 32 + mt * 16 + rg;
        #pragma unroll
        for (int nt = 0; nt < 8; nt++) {
            const int h0 = wn * 64 + nt * 8 + tig * 2;
            float g0 = __ldg(&g_buf[brow * H_ + h0]);
            float g1 = __ldg(&g_buf[brow * H_ + h0 + 1]);
            float g2 = __ldg(&g_buf[(brow + 8) * H_ + h0]);
            float g3 = __ldg(&g_buf[(brow + 8) * H_ + h0 + 1]);
            p0 += acc[mt][nt][0] * g0 + acc[mt][nt][1] * g1;
            p1 += acc[mt][nt][2] * g2 + acc[mt][nt][3] * g3;
        }
        pred[brow][wn * 4 + tig]     = p0;
        pred[brow + 8][wn * 4 + tig] = p1;
    }
    __syncthreads();
    if (t < 128) {
        float s = 0.f;
        #pragma unroll
        for (int cc = 0; cc < 8; cc++) s += pred[t][cc];
        corr_buf[t * G_ + i_cta] = s;     // [b][i] layout (scattered store)
    }
}

// ============================================================================
// K4: y = x/c + (alpha/2)*(corr + Bx)/c^2 ; decoder ; residual. CTA per b.
// Warp-per-output, coalesced float4 reads, shuffle reduce.
// ============================================================================
__global__ __launch_bounds__(256) void k4_dec(
    const float* __restrict__ x,
    const float* __restrict__ dW1, const float* __restrict__ db1,
    const float* __restrict__ dW2, const float* __restrict__ db2,
    float* __restrict__ out)
{
    __shared__ float sx[G_], sy[G_], sd[H_];
    const int b = blockIdx.x, t = threadIdx.x;
    const int lane = t & 31, w = t >> 5;
    const float cinv = 1.0f / (1.0f + 1e-6f);
    const float scale = kAlphaHalf * cinv * cinv;

    #pragma unroll
    for (int q = 0; q < 2; q++) {
        const int i = q * 256 + t;
        const float xv = x[b * G_ + i];
        sx[i] = xv;
        const float corr = corr_buf[b * G_ + i] + bx_buf[b * G_ + i];
        sy[i] = xv * cinv + corr * scale;
    }
    __syncthreads();

    const float4* sy4 = (const float4*)sy;
    #pragma unroll 4
    for (int o = 0; o < 16; o++) {
        const int h = w * 16 + o;
        const float4* wp = (const float4*)(dW1 + h * G_);
        float acc = 0.f;
        #pragma unroll
        for (int k = 0; k < 4; k++) acc += dot4(wp[lane + 32 * k], sy4[lane + 32 * k]);
        acc = wred(acc);
        if (lane == 0) sd[h] = fmaxf(acc + db1[h], 0.f);
    }
    __syncthreads();

    const float4* sd4 = (const float4*)sd;
    #pragma unroll 4
    for (int o = 0; o < 64; o++) {
        const int i = w * 64 + o;
        const float4* wp = (const float4*)(dW2 + i * H_);
        float acc = dot4(wp[lane], sd4[lane]);
        acc = wred(acc);
        if (lane == 0) out[b * G_ + i] = sx[i] + db2[i] + acc;
    }
}

// ============================================================================
extern "C" void kernel_launch(void* const* d_in, const int* in_sizes, int n_in,
                              void* d_out, int out_size)
{
    (void)in_sizes; (void)n_in; (void)out_size;
    const int*   pert  = (const int*)  d_in[0];
    const float* x     = (const float*)d_in[1];
    const float* embW  = (const float*)d_in[2];
    const float* geW1  = (const float*)d_in[3];
    const float* geb1  = (const float*)d_in[4];
    const float* geW2  = (const float*)d_in[5];
    const float* geb2  = (const float*)d_in[6];
    const float* grnW1 = (const float*)d_in[7];
    const float* grnb1 = (const float*)d_in[8];
    const float* grnW2 = (const float*)d_in[9];
    const float* grnb2 = (const float*)d_in[10];
    const float* dW1   = (const float*)d_in[11];
    const float* db1   = (const float*)d_in[12];
    const float* dW2   = (const float*)d_in[13];
    const float* db2   = (const float*)d_in[14];
    float* out = (float*)d_out;

    cudaFuncSetAttribute(k3_main, cudaFuncAttributeMaxDynamicSharedMemorySize,
                         K3_SMEM);

    k1_encode<<<B_, 256>>>(pert, x, embW, geW1, geb1, geW2, geb2, grnW1, grnb1);
    k2_bx<<<64, 256>>>(x, grnb2);
    k3_main<<<G_, 256, K3_SMEM>>>(grnW2);
    k4_dec<<<B_, 256>>>(x, dW1, db1, dW2, db2, out);
}

// round 9
// speedup vs baseline: 3.2192x; 1.3037x over previous
#include <cuda_runtime.h>
#include <cuda_bf16.h>
#include <cstdint>

#define B_ 128
#define G_ 512
#define H_ 128

static __device__ __constant__ float kAlphaHalf = 0.05f;   // ALPHA * 0.5

// ---------------- scratch (static device globals; no allocation) -------------
__device__ float          g_buf[B_ * H_];        // g (B,H) fp32
__device__ __nv_bfloat16  xbf_buf[B_ * G_];      // baseline in bf16 (B,G)
__device__ float          corr_buf[B_ * G_];     // Sum_h g*S, layout [b][i]
__device__ float          bx_buf[B_ * G_];       // Sum_j b2[jG+i] x[b,j], [b][i]

__device__ __forceinline__ float dot4(float4 a, float4 b) {
    return a.x * b.x + a.y * b.y + a.z * b.z + a.w * b.w;
}
template <int U>
__device__ __forceinline__ void wredN(float* a) {
    #pragma unroll
    for (int d = 16; d; d >>= 1)
        #pragma unroll
        for (int u = 0; u < U; u++)
            a[u] += __shfl_xor_sync(0xffffffffu, a[u], d);
}

// ============================================================================
// K1: encoders -> g, plus bf16 copy of baseline. One CTA per sample b.
// Warp computes 4 outputs at a time: batched loads + interleaved reductions.
// ============================================================================
__global__ __launch_bounds__(256) void k1_encode(
    const int*   __restrict__ pert,
    const float* __restrict__ x,
    const float* __restrict__ embW,
    const float* __restrict__ geW1, const float* __restrict__ geb1,
    const float* __restrict__ geW2, const float* __restrict__ geb2,
    const float* __restrict__ grnW1, const float* __restrict__ grnb1)
{
    __shared__ __align__(16) float sx[G_];
    __shared__ __align__(16) float sh[H_];
    __shared__ __align__(16) float sc[2 * H_];
    const int b = blockIdx.x, t = threadIdx.x;
    const int lane = t & 31, w = t >> 5;
    const float* xr = x + b * G_;

    #pragma unroll
    for (int q = 0; q < 2; q++) {
        const int i = q * 256 + t;
        float v = xr[i];
        sx[i] = v;
        xbf_buf[b * G_ + i] = __float2bfloat16(v);
    }
    if (t < 128) sc[t] = embW[pert[b] * H_ + t];
    __syncthreads();

    // phase 1: h = relu(x @ geW1^T + b1), K=512, 16 outputs/warp
    {
        const float4* sx4 = (const float4*)sx;
        float4 xv[4];
        #pragma unroll
        for (int k = 0; k < 4; k++) xv[k] = sx4[lane + 32 * k];
        for (int og = 0; og < 4; og++) {
            const int h = w * 16 + og * 4;
            float a[4];
            #pragma unroll
            for (int u = 0; u < 4; u++) {
                const float4* wp = (const float4*)(geW1 + (h + u) * G_);
                float s = 0.f;
                #pragma unroll
                for (int k = 0; k < 4; k++) s += dot4(wp[lane + 32 * k], xv[k]);
                a[u] = s;
            }
            wredN<4>(a);
            if (lane == 0) {
                #pragma unroll
                for (int u = 0; u < 4; u++)
                    sh[h + u] = fmaxf(a[u] + geb1[h + u], 0.f);
            }
        }
    }
    __syncthreads();

    // phase 2: gene = relu(h @ geW2^T + b2), K=128
    {
        const float4* sh4 = (const float4*)sh;
        float4 hv = sh4[lane];
        for (int og = 0; og < 4; og++) {
            const int h = w * 16 + og * 4;
            float a[4];
            #pragma unroll
            for (int u = 0; u < 4; u++)
                a[u] = dot4(((const float4*)(geW2 + (h + u) * H_))[lane], hv);
            wredN<4>(a);
            if (lane == 0) {
                #pragma unroll
                for (int u = 0; u < 4; u++)
                    sc[H_ + h + u] = fmaxf(a[u] + geb2[h + u], 0.f);
            }
        }
    }
    __syncthreads();

    // phase 3: g = relu([emb|gene] @ grnW1^T + b1), K=256
    {
        const float4* sc4 = (const float4*)sc;
        float4 cv0 = sc4[lane], cv1 = sc4[lane + 32];
        for (int og = 0; og < 4; og++) {
            const int h = w * 16 + og * 4;
            float a[4];
            #pragma unroll
            for (int u = 0; u < 4; u++) {
                const float4* wp = (const float4*)(grnW1 + (h + u) * 2 * H_);
                a[u] = dot4(wp[lane], cv0) + dot4(wp[lane + 32], cv1);
            }
            wredN<4>(a);
            if (lane == 0) {
                #pragma unroll
                for (int u = 0; u < 4; u++)
                    g_buf[b * H_ + h + u] = fmaxf(a[u] + grnb1[h + u], 0.f);
            }
        }
    }
}

// ============================================================================
// K3 (+ folded K2): blocks [0,512) do the big GEMM+epilogue; blocks [512,576)
// compute bx_buf = X @ B2 (grn_b2 viewed [j][i]).
//   C[b,h] = Sum_j X[b,j] * W2[(j*G+i)*H+h]  (128x128x512 bf16 mma)
//   corr[b,i] = Sum_h C[b,h] * g[b,h]        (fused epilogue)
// Depth-3 cp.async pipeline: 4 sA buffers, 3 sW buffers, 2 sB buffers.
// 2 barriers per chunk. HBM: W2 read exactly once (134 MB).
// ============================================================================
__device__ __forceinline__ void ldsm_x4(uint32_t addr, uint32_t& r0, uint32_t& r1,
                                        uint32_t& r2, uint32_t& r3) {
    asm volatile("ldmatrix.sync.aligned.m8n8.x4.shared.b16 {%0,%1,%2,%3},[%4];"
                 : "=r"(r0), "=r"(r1), "=r"(r2), "=r"(r3) : "r"(addr));
}
__device__ __forceinline__ void ldsm_x4_t(uint32_t addr, uint32_t& r0, uint32_t& r1,
                                          uint32_t& r2, uint32_t& r3) {
    asm volatile("ldmatrix.sync.aligned.m8n8.x4.trans.shared.b16 {%0,%1,%2,%3},[%4];"
                 : "=r"(r0), "=r"(r1), "=r"(r2), "=r"(r3) : "r"(addr));
}
__device__ __forceinline__ void cp16(void* dst, const void* src) {
    uint32_t d = (uint32_t)__cvta_generic_to_shared(dst);
    asm volatile("cp.async.cg.shared.global [%0],[%1],16;\n" :: "r"(d), "l"(src));
}
#define MMA16816(d, a, b0r, b1r)                                            \
    asm volatile(                                                           \
        "mma.sync.aligned.m16n8k16.row.col.f32.bf16.bf16.f32 "              \
        "{%0,%1,%2,%3},{%4,%5,%6,%7},{%8,%9},{%0,%1,%2,%3};"                \
        : "+f"((d)[0]), "+f"((d)[1]), "+f"((d)[2]), "+f"((d)[3])            \
        : "r"((a)[0]), "r"((a)[1]), "r"((a)[2]), "r"((a)[3]),               \
          "r"(b0r), "r"(b1r))

#define K3_CH   32
#define K3_NCH  16
#define K3_PA   40
#define K3_PB   136
// dynamic smem layout (bytes)
#define K3_SA_OFF   0                       // 4 * 128*40*2  = 40960
#define K3_SW_OFF   40960                   // 3 * 32*128*4  = 49152
#define K3_SB_OFF   90112                   // 2 * 32*136*2  = 17408
#define K3_PRED_OFF 107520                  // 128*8*4       = 4096
#define K3_SMEM     111616

__global__ __launch_bounds__(256, 2) void k3_main(
    const float* __restrict__ W2,
    const float* __restrict__ x,
    const float* __restrict__ b2)
{
    extern __shared__ char smem[];
    const int t = threadIdx.x;

    // ---------------- folded K2: bx_buf = X @ B2 ----------------------------
    if (blockIdx.x >= G_) {
        float* sX = (float*)smem;                                // [16][512]
        float (*sB2)[64] = (float (*)[64])(smem + 16 * G_ * 4);  // [32][64]
        const int blk = blockIdx.x - G_;
        const int bc = blk >> 3, ic = blk & 7;
        const int b0 = bc * 16, i0 = ic * 64;
        const int i_loc = t & 63, bgrp = t >> 6;

        for (int idx = t; idx < 16 * 128; idx += 256) {
            const int r = idx >> 7, c4 = idx & 127;
            ((float4*)(sX + r * G_))[c4] = *(const float4*)(x + (b0 + r) * G_ + c4 * 4);
        }
        float acc[4] = {0.f, 0.f, 0.f, 0.f};
        for (int jc = 0; jc < 16; jc++) {
            __syncthreads();
            for (int idx = t; idx < 32 * 16; idx += 256) {
                const int r = idx >> 4, q = idx & 15;
                ((float4*)sB2[r])[q] = *(const float4*)(b2 + (jc * 32 + r) * G_ + i0 + q * 4);
            }
            __syncthreads();
            #pragma unroll 8
            for (int j = 0; j < 32; j++) {
                const float bv = sB2[j][i_loc];
                #pragma unroll
                for (int r = 0; r < 4; r++)
                    acc[r] += bv * sX[(bgrp * 4 + r) * G_ + jc * 32 + j];
            }
        }
        #pragma unroll
        for (int r = 0; r < 4; r++)
            bx_buf[(b0 + bgrp * 4 + r) * G_ + i0 + i_loc] = acc[r];
        return;
    }

    // ---------------- main GEMM path ----------------------------------------
    __nv_bfloat16* sA = (__nv_bfloat16*)(smem + K3_SA_OFF);  // [4][128*PA]
    float*         sW = (float*)(smem + K3_SW_OFF);          // [3][32*128]
    __nv_bfloat16* sB = (__nv_bfloat16*)(smem + K3_SB_OFF);  // [2][32*PB]
    float (*pred)[8]  = (float (*)[8])(smem + K3_PRED_OFF);  // [128][8]

    const int i_cta = blockIdx.x;
    const int lane = t & 31, w = t >> 5;
    const int wm = w & 3, wn = w >> 2;

    float acc[2][8][4];
    #pragma unroll
    for (int mt = 0; mt < 2; mt++)
        #pragma unroll
        for (int nt = 0; nt < 8; nt++)
            #pragma unroll
            for (int r = 0; r < 4; r++) acc[mt][nt][r] = 0.f;

    auto issue = [&](int c) {
        if (c >= K3_NCH) return;
        __nv_bfloat16* sAb = sA + (c & 3) * 128 * K3_PA;
        float*         sWb = sW + (c % 3) * K3_CH * H_;
        const int j0 = c * K3_CH;
        #pragma unroll
        for (int k = 0; k < 2; k++) {
            const int idx = t + k * 256;
            const int r = idx >> 2, q = idx & 3;
            cp16(&sAb[r * K3_PA + q * 8], &xbf_buf[r * G_ + j0 + q * 8]);
        }
        #pragma unroll
        for (int k = 0; k < 4; k++) {
            const int idx = t + k * 256;
            const int r = idx >> 5, q = idx & 31;
            cp16(&sWb[r * H_ + q * 4],
                 W2 + ((long)(j0 + r) * G_ + i_cta) * H_ + q * 4);
        }
        asm volatile("cp.async.commit_group;\n" ::: "memory");
    };

    issue(0); issue(1); issue(2);
    for (int c = 0; c < K3_NCH; c++) {
        if (c < K3_NCH - 2)
            asm volatile("cp.async.wait_group 2;\n" ::: "memory");
        else if (c == K3_NCH - 2)
            asm volatile("cp.async.wait_group 1;\n" ::: "memory");
        else
            asm volatile("cp.async.wait_group 0;\n" ::: "memory");
        __syncthreads();   // chunk c visible; mma(c-1) done

        // convert sW[c%3] (fp32) -> sB[c&1] (bf16); 16 floats/thread
        {
            const float* wsrc = sW + (c % 3) * K3_CH * H_;
            __nv_bfloat16* sBb = sB + (c & 1) * K3_CH * K3_PB;
            const int r = t >> 3, c0 = (t & 7) * 16;
            const float4* src = (const float4*)(wsrc + r * H_ + c0);
            float4 v0 = src[0], v1 = src[1], v2 = src[2], v3 = src[3];
            __nv_bfloat162 p0 = __floats2bfloat162_rn(v0.x, v0.y);
            __nv_bfloat162 p1 = __floats2bfloat162_rn(v0.z, v0.w);
            __nv_bfloat162 p2 = __floats2bfloat162_rn(v1.x, v1.y);
            __nv_bfloat162 p3 = __floats2bfloat162_rn(v1.z, v1.w);
            __nv_bfloat162 p4 = __floats2bfloat162_rn(v2.x, v2.y);
            __nv_bfloat162 p5 = __floats2bfloat162_rn(v2.z, v2.w);
            __nv_bfloat162 p6 = __floats2bfloat162_rn(v3.x, v3.y);
            __nv_bfloat162 p7 = __floats2bfloat162_rn(v3.z, v3.w);
            uint4 o0, o1;
            o0.x = *(uint32_t*)&p0; o0.y = *(uint32_t*)&p1;
            o0.z = *(uint32_t*)&p2; o0.w = *(uint32_t*)&p3;
            o1.x = *(uint32_t*)&p4; o1.y = *(uint32_t*)&p5;
            o1.z = *(uint32_t*)&p6; o1.w = *(uint32_t*)&p7;
            *(uint4*)&sBb[r * K3_PB + c0]     = o0;
            *(uint4*)&sBb[r * K3_PB + c0 + 8] = o1;
        }
        __syncthreads();   // convert visible

        const __nv_bfloat16* sAc = sA + (c & 3) * 128 * K3_PA;
        const __nv_bfloat16* sBc = sB + (c & 1) * K3_CH * K3_PB;
        #pragma unroll
        for (int ks = 0; ks < K3_CH; ks += 16) {
            uint32_t afr[2][4];
            #pragma unroll
            for (int mt = 0; mt < 2; mt++) {
                const int row = wm * 32 + mt * 16 + (lane & 15);
                const int col = ks + ((lane >> 4) << 3);
                uint32_t a = (uint32_t)__cvta_generic_to_shared(&sAc[row * K3_PA + col]);
                ldsm_x4(a, afr[mt][0], afr[mt][1], afr[mt][2], afr[mt][3]);
            }
            uint32_t bfr[4][4];
            #pragma unroll
            for (int n4 = 0; n4 < 4; n4++) {
                const int krow = ks + (lane & 15);
                const int col = wn * 64 + n4 * 16 + ((lane >> 4) << 3);
                uint32_t a = (uint32_t)__cvta_generic_to_shared(&sBc[krow * K3_PB + col]);
                ldsm_x4_t(a, bfr[n4][0], bfr[n4][1], bfr[n4][2], bfr[n4][3]);
            }
            #pragma unroll
            for (int mt = 0; mt < 2; mt++)
                #pragma unroll
                for (int nt = 0; nt < 8; nt++) {
                    const int n4 = nt >> 1, p = (nt & 1) * 2;
                    MMA16816(acc[mt][nt], afr[mt], bfr[n4][p], bfr[n4][p + 1]);
                }
        }
        issue(c + 3);      // sA[(c+3)&3] free (mma(c-1) done at bar above)
    }

    // epilogue: corr[b,i_cta] = Sum_h C[b,h]*g[b,h] (deterministic)
    const int rg = lane >> 2, tig = lane & 3;
    #pragma unroll
    for (int mt = 0; mt < 2; mt++) {
        float p0 = 0.f, p1 = 0.f;
        const int brow = wm * 32 + mt * 16 + rg;
        #pragma unroll
        for (int nt = 0; nt < 8; nt++) {
            const int h0 = wn * 64 + nt * 8 + tig * 2;
            float g0 = __ldg(&g_buf[brow * H_ + h0]);
            float g1 = __ldg(&g_buf[brow * H_ + h0 + 1]);
            float g2 = __ldg(&g_buf[(brow + 8) * H_ + h0]);
            float g3 = __ldg(&g_buf[(brow + 8) * H_ + h0 + 1]);
            p0 += acc[mt][nt][0] * g0 + acc[mt][nt][1] * g1;
            p1 += acc[mt][nt][2] * g2 + acc[mt][nt][3] * g3;
        }
        pred[brow][wn * 4 + tig]     = p0;
        pred[brow + 8][wn * 4 + tig] = p1;
    }
    __syncthreads();
    if (t < 128) {
        float s = 0.f;
        #pragma unroll
        for (int cc = 0; cc < 8; cc++) s += pred[t][cc];
        corr_buf[t * G_ + i_cta] = s;     // [b][i] layout
    }
}

// ============================================================================
// K4: y = x/c + (alpha/2)*(corr + Bx)/c^2 ; decoder ; residual. CTA per b.
// Batched loads + interleaved warp reductions (U=4 and U=8).
// ============================================================================
__global__ __launch_bounds__(256) void k4_dec(
    const float* __restrict__ x,
    const float* __restrict__ dW1, const float* __restrict__ db1,
    const float* __restrict__ dW2, const float* __restrict__ db2,
    float* __restrict__ out)
{
    __shared__ __align__(16) float sx[G_];
    __shared__ __align__(16) float sy[G_];
    __shared__ __align__(16) float sd[H_];
    const int b = blockIdx.x, t = threadIdx.x;
    const int lane = t & 31, w = t >> 5;
    const float cinv = 1.0f / (1.0f + 1e-6f);
    const float scale = kAlphaHalf * cinv * cinv;

    #pragma unroll
    for (int q = 0; q < 2; q++) {
        const int i = q * 256 + t;
        const float xv = x[b * G_ + i];
        sx[i] = xv;
        const float corr = corr_buf[b * G_ + i] + bx_buf[b * G_ + i];
        sy[i] = xv * cinv + corr * scale;
    }
    __syncthreads();

    // d = relu(y @ dW1^T + b1), K=512, 16 outputs/warp
    {
        const float4* sy4 = (const float4*)sy;
        float4 yv[4];
        #pragma unroll
        for (int k = 0; k < 4; k++) yv[k] = sy4[lane + 32 * k];
        for (int og = 0; og < 4; og++) {
            const int h = w * 16 + og * 4;
            float a[4];
            #pragma unroll
            for (int u = 0; u < 4; u++) {
                const float4* wp = (const float4*)(dW1 + (h + u) * G_);
                float s = 0.f;
                #pragma unroll
                for (int k = 0; k < 4; k++) s += dot4(wp[lane + 32 * k], yv[k]);
                a[u] = s;
            }
            wredN<4>(a);
            if (lane == 0) {
                #pragma unroll
                for (int u = 0; u < 4; u++)
                    sd[h + u] = fmaxf(a[u] + db1[h + u], 0.f);
            }
        }
    }
    __syncthreads();

    // out = x + d @ dW2^T + b2, K=128, 64 outputs/warp, U=8
    {
        const float4* sd4 = (const float4*)sd;
        float4 dv = sd4[lane];
        for (int og = 0; og < 8; og++) {
            const int i = w * 64 + og * 8;
            float a[8];
            #pragma unroll
            for (int u = 0; u < 8; u++)
                a[u] = dot4(((const float4*)(dW2 + (i + u) * H_))[lane], dv);
            wredN<8>(a);
            if (lane == 0) {
                #pragma unroll
                for (int u = 0; u < 8; u++)
                    out[b * G_ + i + u] = sx[i + u] + db2[i + u] + a[u];
            }
        }
    }
}

// ============================================================================
extern "C" void kernel_launch(void* const* d_in, const int* in_sizes, int n_in,
                              void* d_out, int out_size)
{
    (void)in_sizes; (void)n_in; (void)out_size;
    const int*   pert  = (const int*)  d_in[0];
    const float* x     = (const float*)d_in[1];
    const float* embW  = (const float*)d_in[2];
    const float* geW1  = (const float*)d_in[3];
    const float* geb1  = (const float*)d_in[4];
    const float* geW2  = (const float*)d_in[5];
    const float* geb2  = (const float*)d_in[6];
    const float* grnW1 = (const float*)d_in[7];
    const float* grnb1 = (const float*)d_in[8];
    const float* grnW2 = (const float*)d_in[9];
    const float* grnb2 = (const float*)d_in[10];
    const float* dW1   = (const float*)d_in[11];
    const float* db1   = (const float*)d_in[12];
    const float* dW2   = (const float*)d_in[13];
    const float* db2   = (const float*)d_in[14];
    float* out = (float*)d_out;

    cudaFuncSetAttribute(k3_main, cudaFuncAttributeMaxDynamicSharedMemorySize,
                         K3_SMEM);

    k1_encode<<<B_, 256>>>(pert, x, embW, geW1, geb1, geW2, geb2, grnW1, grnb1);
    k3_main<<<G_ + 64, 256, K3_SMEM>>>(grnW2, x, grnb2);
    k4_dec<<<B_, 256>>>(x, dW1, db1, dW2, db2, out);
}

// round 11
// speedup vs baseline: 3.8080x; 1.1829x over previous
#include <cuda_runtime.h>
#include <cuda_bf16.h>
#include <cstdint>

#define B_ 128
#define G_ 512
#define H_ 128

static __device__ __constant__ float kAlphaHalf = 0.05f;   // ALPHA * 0.5

// ---------------- scratch (static device globals; no allocation) -------------
__device__ float          g_buf[B_ * H_];        // g (B,H) fp32
__device__ __nv_bfloat16  xbf_buf[B_ * G_];      // baseline in bf16 (B,G)
__device__ float          corr_buf[B_ * G_];     // Sum_h g*S, layout [b][i]
__device__ float          bx_buf[B_ * G_];       // Sum_j b2[jG+i] x[b,j], [b][i]

__device__ __forceinline__ float dot4(float4 a, float4 b) {
    return a.x * b.x + a.y * b.y + a.z * b.z + a.w * b.w;
}
template <int U>
__device__ __forceinline__ void wredN(float* a) {
    #pragma unroll
    for (int d = 16; d; d >>= 1)
        #pragma unroll
        for (int u = 0; u < U; u++)
            a[u] += __shfl_xor_sync(0xffffffffu, a[u], d);
}

// ============================================================================
// K1: encoders -> g, plus bf16 copy of baseline. One CTA per sample b.
// 1024 threads (32 warps): 4 outputs per warp per phase -> latency hidden.
// ============================================================================
__global__ __launch_bounds__(1024) void k1_encode(
    const int*   __restrict__ pert,
    const float* __restrict__ x,
    const float* __restrict__ embW,
    const float* __restrict__ geW1, const float* __restrict__ geb1,
    const float* __restrict__ geW2, const float* __restrict__ geb2,
    const float* __restrict__ grnW1, const float* __restrict__ grnb1)
{
    __shared__ __align__(16) float sx[G_];
    __shared__ __align__(16) float sh[H_];
    __shared__ __align__(16) float sc[2 * H_];
    const int b = blockIdx.x, t = threadIdx.x;
    const int lane = t & 31, w = t >> 5;
    const float* xr = x + b * G_;

    if (t < G_) {
        float v = xr[t];
        sx[t] = v;
        xbf_buf[b * G_ + t] = __float2bfloat16(v);
    }
    if (t < H_) sc[t] = embW[pert[b] * H_ + t];
    __syncthreads();

    // phase 1: h = relu(x @ geW1^T + b1), K=512; 4 outputs/warp
    {
        const float4* sx4 = (const float4*)sx;
        float4 xv[4];
        #pragma unroll
        for (int k = 0; k < 4; k++) xv[k] = sx4[lane + 32 * k];
        const int h = w * 4;
        float a[4];
        #pragma unroll
        for (int u = 0; u < 4; u++) {
            const float4* wp = (const float4*)(geW1 + (h + u) * G_);
            float s = 0.f;
            #pragma unroll
            for (int k = 0; k < 4; k++) s += dot4(wp[lane + 32 * k], xv[k]);
            a[u] = s;
        }
        wredN<4>(a);
        if (lane == 0) {
            #pragma unroll
            for (int u = 0; u < 4; u++)
                sh[h + u] = fmaxf(a[u] + geb1[h + u], 0.f);
        }
    }
    __syncthreads();

    // phase 2: gene = relu(h @ geW2^T + b2), K=128; 4 outputs/warp
    {
        const float4* sh4 = (const float4*)sh;
        float4 hv = sh4[lane];
        const int h = w * 4;
        float a[4];
        #pragma unroll
        for (int u = 0; u < 4; u++)
            a[u] = dot4(((const float4*)(geW2 + (h + u) * H_))[lane], hv);
        wredN<4>(a);
        if (lane == 0) {
            #pragma unroll
            for (int u = 0; u < 4; u++)
                sc[H_ + h + u] = fmaxf(a[u] + geb2[h + u], 0.f);
        }
    }
    __syncthreads();

    // phase 3: g = relu([emb|gene] @ grnW1^T + b1), K=256; 4 outputs/warp
    {
        const float4* sc4 = (const float4*)sc;
        float4 cv0 = sc4[lane], cv1 = sc4[lane + 32];
        const int h = w * 4;
        float a[4];
        #pragma unroll
        for (int u = 0; u < 4; u++) {
            const float4* wp = (const float4*)(grnW1 + (h + u) * 2 * H_);
            a[u] = dot4(wp[lane], cv0) + dot4(wp[lane + 32], cv1);
        }
        wredN<4>(a);
        if (lane == 0) {
            #pragma unroll
            for (int u = 0; u < 4; u++)
                g_buf[b * H_ + h + u] = fmaxf(a[u] + grnb1[h + u], 0.f);
        }
    }
}

// ============================================================================
// K3 (+ folded K2): blocks [0,512) do the big GEMM+epilogue; blocks [512,576)
// compute bx_buf = X @ B2 (grn_b2 viewed [j][i]).
//   C[b,h] = Sum_j X[b,j] * W2[(j*G+i)*H+h]  (128x128x512 bf16 mma)
//   corr[b,i] = Sum_h C[b,h] * g[b,h]        (fused epilogue)
// Depth-3 cp.async pipeline; self-owned W2 copies -> convert needs no barrier;
// exactly ONE __syncthreads per chunk. HBM: W2 read exactly once (134 MB).
// ============================================================================
__device__ __forceinline__ void ldsm_x4(uint32_t addr, uint32_t& r0, uint32_t& r1,
                                        uint32_t& r2, uint32_t& r3) {
    asm volatile("ldmatrix.sync.aligned.m8n8.x4.shared.b16 {%0,%1,%2,%3},[%4];"
                 : "=r"(r0), "=r"(r1), "=r"(r2), "=r"(r3) : "r"(addr));
}
__device__ __forceinline__ void ldsm_x4_t(uint32_t addr, uint32_t& r0, uint32_t& r1,
                                          uint32_t& r2, uint32_t& r3) {
    asm volatile("ldmatrix.sync.aligned.m8n8.x4.trans.shared.b16 {%0,%1,%2,%3},[%4];"
                 : "=r"(r0), "=r"(r1), "=r"(r2), "=r"(r3) : "r"(addr));
}
__device__ __forceinline__ void cp16(void* dst, const void* src) {
    uint32_t d = (uint32_t)__cvta_generic_to_shared(dst);
    asm volatile("cp.async.cg.shared.global [%0],[%1],16;\n" :: "r"(d), "l"(src));
}
#define MMA16816(d, a, b0r, b1r)                                            \
    asm volatile(                                                           \
        "mma.sync.aligned.m16n8k16.row.col.f32.bf16.bf16.f32 "              \
        "{%0,%1,%2,%3},{%4,%5,%6,%7},{%8,%9},{%0,%1,%2,%3};"                \
        : "+f"((d)[0]), "+f"((d)[1]), "+f"((d)[2]), "+f"((d)[3])            \
        : "r"((a)[0]), "r"((a)[1]), "r"((a)[2]), "r"((a)[3]),               \
          "r"(b0r), "r"(b1r))

#define K3_CH   32
#define K3_NCH  16
#define K3_PA   40
#define K3_PB   136
// dynamic smem layout (bytes)
#define K3_SA_OFF   0                       // 4 * 128*40*2  = 40960
#define K3_SW_OFF   40960                   // 3 * 32*128*4  = 49152
#define K3_SB_OFF   90112                   // 2 * 32*136*2  = 17408
#define K3_PRED_OFF 107520                  // 128*8*4       = 4096
#define K3_SMEM     111616

__global__ __launch_bounds__(256, 2) void k3_main(
    const float* __restrict__ W2,
    const float* __restrict__ x,
    const float* __restrict__ b2)
{
    extern __shared__ char smem[];
    const int t = threadIdx.x;

    // ---------------- folded K2: bx_buf = X @ B2 ----------------------------
    if (blockIdx.x >= G_) {
        float* sX = (float*)smem;                                // [16][512]
        float (*sB2)[64] = (float (*)[64])(smem + 16 * G_ * 4);  // [32][64]
        const int blk = blockIdx.x - G_;
        const int bc = blk >> 3, ic = blk & 7;
        const int b0 = bc * 16, i0 = ic * 64;
        const int i_loc = t & 63, bgrp = t >> 6;

        for (int idx = t; idx < 16 * 128; idx += 256) {
            const int r = idx >> 7, c4 = idx & 127;
            ((float4*)(sX + r * G_))[c4] = *(const float4*)(x + (b0 + r) * G_ + c4 * 4);
        }
        float acc[4] = {0.f, 0.f, 0.f, 0.f};
        for (int jc = 0; jc < 16; jc++) {
            __syncthreads();
            for (int idx = t; idx < 32 * 16; idx += 256) {
                const int r = idx >> 4, q = idx & 15;
                ((float4*)sB2[r])[q] = *(const float4*)(b2 + (jc * 32 + r) * G_ + i0 + q * 4);
            }
            __syncthreads();
            #pragma unroll 8
            for (int j = 0; j < 32; j++) {
                const float bv = sB2[j][i_loc];
                #pragma unroll
                for (int r = 0; r < 4; r++)
                    acc[r] += bv * sX[(bgrp * 4 + r) * G_ + jc * 32 + j];
            }
        }
        #pragma unroll
        for (int r = 0; r < 4; r++)
            bx_buf[(b0 + bgrp * 4 + r) * G_ + i0 + i_loc] = acc[r];
        return;
    }

    // ---------------- main GEMM path ----------------------------------------
    __nv_bfloat16* sA = (__nv_bfloat16*)(smem + K3_SA_OFF);  // [4][128*PA]
    float*         sW = (float*)(smem + K3_SW_OFF);          // [3][32*128]
    __nv_bfloat16* sB = (__nv_bfloat16*)(smem + K3_SB_OFF);  // [2][32*PB]
    float (*pred)[8]  = (float (*)[8])(smem + K3_PRED_OFF);  // [128][8]

    const int i_cta = blockIdx.x;
    const int lane = t & 31, w = t >> 5;
    const int wm = w & 3, wn = w >> 2;
    const int wrow = t >> 3;            // 0..31: W2 row this thread owns
    const int wcol = (t & 7) * 16;      // 16 consecutive floats

    float acc[2][8][4];
    #pragma unroll
    for (int mt = 0; mt < 2; mt++)
        #pragma unroll
        for (int nt = 0; nt < 8; nt++)
            #pragma unroll
            for (int r = 0; r < 4; r++) acc[mt][nt][r] = 0.f;

    auto issue = [&](int c) {
        if (c >= K3_NCH) return;
        __nv_bfloat16* sAb = sA + (c & 3) * 128 * K3_PA;
        float*         sWb = sW + (c % 3) * K3_CH * H_;
        const int j0 = c * K3_CH;
        #pragma unroll
        for (int k = 0; k < 2; k++) {
            const int idx = t + k * 256;
            const int r = idx >> 2, q = idx & 3;
            cp16(&sAb[r * K3_PA + q * 8], &xbf_buf[r * G_ + j0 + q * 8]);
        }
        // each thread copies the exact 16 floats it will later convert
        const float* gsrc = W2 + ((long)(j0 + wrow) * G_ + i_cta) * H_ + wcol;
        float* ssrc = sWb + wrow * H_ + wcol;
        #pragma unroll
        for (int k = 0; k < 4; k++) cp16(ssrc + k * 4, gsrc + k * 4);
        asm volatile("cp.async.commit_group;\n" ::: "memory");
    };

    issue(0); issue(1); issue(2);
    for (int c = 0; c < K3_NCH; c++) {
        if (c < K3_NCH - 2)
            asm volatile("cp.async.wait_group 2;\n" ::: "memory");
        else if (c == K3_NCH - 2)
            asm volatile("cp.async.wait_group 1;\n" ::: "memory");
        else
            asm volatile("cp.async.wait_group 0;\n" ::: "memory");

        // convert OWN fp32 copies (visible to self after wait) -> bf16 STS
        {
            const float* src = sW + (c % 3) * K3_CH * H_ + wrow * H_ + wcol;
            __nv_bfloat16* sBb = sB + (c & 1) * K3_CH * K3_PB;
            float4 v0 = ((const float4*)src)[0];
            float4 v1 = ((const float4*)src)[1];
            float4 v2 = ((const float4*)src)[2];
            float4 v3 = ((const float4*)src)[3];
            __nv_bfloat162 p0 = __floats2bfloat162_rn(v0.x, v0.y);
            __nv_bfloat162 p1 = __floats2bfloat162_rn(v0.z, v0.w);
            __nv_bfloat162 p2 = __floats2bfloat162_rn(v1.x, v1.y);
            __nv_bfloat162 p3 = __floats2bfloat162_rn(v1.z, v1.w);
            __nv_bfloat162 p4 = __floats2bfloat162_rn(v2.x, v2.y);
            __nv_bfloat162 p5 = __floats2bfloat162_rn(v2.z, v2.w);
            __nv_bfloat162 p6 = __floats2bfloat162_rn(v3.x, v3.y);
            __nv_bfloat162 p7 = __floats2bfloat162_rn(v3.z, v3.w);
            uint4 o0, o1;
            o0.x = *(uint32_t*)&p0; o0.y = *(uint32_t*)&p1;
            o0.z = *(uint32_t*)&p2; o0.w = *(uint32_t*)&p3;
            o1.x = *(uint32_t*)&p4; o1.y = *(uint32_t*)&p5;
            o1.z = *(uint32_t*)&p6; o1.w = *(uint32_t*)&p7;
            *(uint4*)&sBb[wrow * K3_PB + wcol]     = o0;
            *(uint4*)&sBb[wrow * K3_PB + wcol + 8] = o1;
        }
        __syncthreads();   // the ONLY barrier per chunk: all copies+converts visible

        const __nv_bfloat16* sAc = sA + (c & 3) * 128 * K3_PA;
        const __nv_bfloat16* sBc = sB + (c & 1) * K3_CH * K3_PB;
        #pragma unroll
        for (int ks = 0; ks < K3_CH; ks += 16) {
            uint32_t afr[2][4];
            #pragma unroll
            for (int mt = 0; mt < 2; mt++) {
                const int row = wm * 32 + mt * 16 + (lane & 15);
                const int col = ks + ((lane >> 4) << 3);
                uint32_t a = (uint32_t)__cvta_generic_to_shared(&sAc[row * K3_PA + col]);
                ldsm_x4(a, afr[mt][0], afr[mt][1], afr[mt][2], afr[mt][3]);
            }
            uint32_t bfr[4][4];
            #pragma unroll
            for (int n4 = 0; n4 < 4; n4++) {
                const int krow = ks + (lane & 15);
                const int col = wn * 64 + n4 * 16 + ((lane >> 4) << 3);
                uint32_t a = (uint32_t)__cvta_generic_to_shared(&sBc[krow * K3_PB + col]);
                ldsm_x4_t(a, bfr[n4][0], bfr[n4][1], bfr[n4][2], bfr[n4][3]);
            }
            #pragma unroll
            for (int mt = 0; mt < 2; mt++)
                #pragma unroll
                for (int nt = 0; nt < 8; nt++) {
                    const int n4 = nt >> 1, p = (nt & 1) * 2;
                    MMA16816(acc[mt][nt], afr[mt], bfr[n4][p], bfr[n4][p + 1]);
                }
        }
        issue(c + 3);      // safe: all warps finished MMA(c-1) before this bar
    }

    // epilogue: corr[b,i_cta] = Sum_h C[b,h]*g[b,h] (deterministic)
    const int rg = lane >> 2, tig = lane & 3;
    #pragma unroll
    for (int mt = 0; mt < 2; mt++) {
        float p0 = 0.f, p1 = 0.f;
        const int brow = wm * 32 + mt * 16 + rg;
        #pragma unroll
        for (int nt = 0; nt < 8; nt++) {
            const int h0 = wn * 64 + nt * 8 + tig * 2;
            float g0 = __ldg(&g_buf[brow * H_ + h0]);
            float g1 = __ldg(&g_buf[brow * H_ + h0 + 1]);
            float g2 = __ldg(&g_buf[(brow + 8) * H_ + h0]);
            float g3 = __ldg(&g_buf[(brow + 8) * H_ + h0 + 1]);
            p0 += acc[mt][nt][0] * g0 + acc[mt][nt][1] * g1;
            p1 += acc[mt][nt][2] * g2 + acc[mt][nt][3] * g3;
        }
        pred[brow][wn * 4 + tig]     = p0;
        pred[brow + 8][wn * 4 + tig] = p1;
    }
    __syncthreads();
    if (t < 128) {
        float s = 0.f;
        #pragma unroll
        for (int cc = 0; cc < 8; cc++) s += pred[t][cc];
        corr_buf[t * G_ + i_cta] = s;     // [b][i] layout
    }
}

// ============================================================================
// K4: y = x/c + (alpha/2)*(corr + Bx)/c^2 ; decoder ; residual. CTA per b.
// 1024 threads (32 warps): 4 (then 16) outputs per warp.
// ============================================================================
__global__ __launch_bounds__(1024) void k4_dec(
    const float* __restrict__ x,
    const float* __restrict__ dW1, const float* __restrict__ db1,
    const float* __restrict__ dW2, const float* __restrict__ db2,
    float* __restrict__ out)
{
    __shared__ __align__(16) float sx[G_];
    __shared__ __align__(16) float sy[G_];
    __shared__ __align__(16) float sd[H_];
    const int b = blockIdx.x, t = threadIdx.x;
    const int lane = t & 31, w = t >> 5;
    const float cinv = 1.0f / (1.0f + 1e-6f);
    const float scale = kAlphaHalf * cinv * cinv;

    if (t < G_) {
        const float xv = x[b * G_ + t];
        sx[t] = xv;
        const float corr = corr_buf[b * G_ + t] + bx_buf[b * G_ + t];
        sy[t] = xv * cinv + corr * scale;
    }
    __syncthreads();

    // d = relu(y @ dW1^T + b1), K=512; 4 outputs/warp
    {
        const float4* sy4 = (const float4*)sy;
        float4 yv[4];
        #pragma unroll
        for (int k = 0; k < 4; k++) yv[k] = sy4[lane + 32 * k];
        const int h = w * 4;
        float a[4];
        #pragma unroll
        for (int u = 0; u < 4; u++) {
            const float4* wp = (const float4*)(dW1 + (h + u) * G_);
            float s = 0.f;
            #pragma unroll
            for (int k = 0; k < 4; k++) s += dot4(wp[lane + 32 * k], yv[k]);
            a[u] = s;
        }
        wredN<4>(a);
        if (lane == 0) {
            #pragma unroll
            for (int u = 0; u < 4; u++)
                sd[h + u] = fmaxf(a[u] + db1[h + u], 0.f);
        }
    }
    __syncthreads();

    // out = x + d @ dW2^T + b2, K=128; 16 outputs/warp (2 groups of U=8)
    {
        const float4* sd4 = (const float4*)sd;
        float4 dv = sd4[lane];
        #pragma unroll
        for (int og = 0; og < 2; og++) {
            const int i = w * 16 + og * 8;
            float a[8];
            #pragma unroll
            for (int u = 0; u < 8; u++)
                a[u] = dot4(((const float4*)(dW2 + (i + u) * H_))[lane], dv);
            wredN<8>(a);
            if (lane == 0) {
                #pragma unroll
                for (int u = 0; u < 8; u++)
                    out[b * G_ + i + u] = sx[i + u] + db2[i + u] + a[u];
            }
        }
    }
}

// ============================================================================
extern "C" void kernel_launch(void* const* d_in, const int* in_sizes, int n_in,
                              void* d_out, int out_size)
{
    (void)in_sizes; (void)n_in; (void)out_size;
    const int*   pert  = (const int*)  d_in[0];
    const float* x     = (const float*)d_in[1];
    const float* embW  = (const float*)d_in[2];
    const float* geW1  = (const float*)d_in[3];
    const float* geb1  = (const float*)d_in[4];
    const float* geW2  = (const float*)d_in[5];
    const float* geb2  = (const float*)d_in[6];
    const float* grnW1 = (const float*)d_in[7];
    const float* grnb1 = (const float*)d_in[8];
    const float* grnW2 = (const float*)d_in[9];
    const float* grnb2 = (const float*)d_in[10];
    const float* dW1   = (const float*)d_in[11];
    const float* db1   = (const float*)d_in[12];
    const float* dW2   = (const float*)d_in[13];
    const float* db2   = (const float*)d_in[14];
    float* out = (float*)d_out;

    cudaFuncSetAttribute(k3_main, cudaFuncAttributeMaxDynamicSharedMemorySize,
                         K3_SMEM);

    k1_encode<<<B_, 1024>>>(pert, x, embW, geW1, geb1, geW2, geb2, grnW1, grnb1);
    k3_main<<<G_ + 64, 256, K3_SMEM>>>(grnW2, x, grnb2);
    k4_dec<<<B_, 1024>>>(x, dW1, db1, dW2, db2, out);
}

// round 12
// speedup vs baseline: 4.3772x; 1.1495x over previous
#include <cuda_runtime.h>
#include <cuda_bf16.h>
#include <cstdint>

#define B_ 128
#define G_ 512
#define H_ 128

static __device__ __constant__ float kAlphaHalf = 0.05f;   // ALPHA * 0.5

// ---------------- scratch (static device globals; no allocation) -------------
__device__ float          g_buf[B_ * H_];        // g (B,H) fp32
__device__ __nv_bfloat16  xbf_buf[B_ * G_];      // baseline in bf16 (B,G)
__device__ float          corr_buf[B_ * G_];     // Sum_h g*S, layout [b][i]
__device__ float          bx_buf[B_ * G_];       // Sum_j b2[jG+i] x[b,j], [b][i]

__device__ __forceinline__ float dot4(float4 a, float4 b) {
    return a.x * b.x + a.y * b.y + a.z * b.z + a.w * b.w;
}
template <int U>
__device__ __forceinline__ void wredN(float* a) {
    #pragma unroll
    for (int d = 16; d; d >>= 1)
        #pragma unroll
        for (int u = 0; u < U; u++)
            a[u] += __shfl_xor_sync(0xffffffffu, a[u], d);
}

// ============================================================================
// K1: encoders -> g, plus bf16 copy of baseline. One CTA per sample b.
// 1024 threads (32 warps): 4 outputs per warp per phase.
// ============================================================================
__global__ __launch_bounds__(1024) void k1_encode(
    const int*   __restrict__ pert,
    const float* __restrict__ x,
    const float* __restrict__ embW,
    const float* __restrict__ geW1, const float* __restrict__ geb1,
    const float* __restrict__ geW2, const float* __restrict__ geb2,
    const float* __restrict__ grnW1, const float* __restrict__ grnb1)
{
    __shared__ __align__(16) float sx[G_];
    __shared__ __align__(16) float sh[H_];
    __shared__ __align__(16) float sc[2 * H_];
    const int b = blockIdx.x, t = threadIdx.x;
    const int lane = t & 31, w = t >> 5;
    const float* xr = x + b * G_;

    if (t < G_) {
        float v = xr[t];
        sx[t] = v;
        xbf_buf[b * G_ + t] = __float2bfloat16(v);
    }
    if (t < H_) sc[t] = embW[pert[b] * H_ + t];
    __syncthreads();

    // phase 1: h = relu(x @ geW1^T + b1), K=512; 4 outputs/warp
    {
        const float4* sx4 = (const float4*)sx;
        float4 xv[4];
        #pragma unroll
        for (int k = 0; k < 4; k++) xv[k] = sx4[lane + 32 * k];
        const int h = w * 4;
        float a[4];
        #pragma unroll
        for (int u = 0; u < 4; u++) {
            const float4* wp = (const float4*)(geW1 + (h + u) * G_);
            float s = 0.f;
            #pragma unroll
            for (int k = 0; k < 4; k++) s += dot4(wp[lane + 32 * k], xv[k]);
            a[u] = s;
        }
        wredN<4>(a);
        if (lane == 0) {
            #pragma unroll
            for (int u = 0; u < 4; u++)
                sh[h + u] = fmaxf(a[u] + geb1[h + u], 0.f);
        }
    }
    __syncthreads();

    // phase 2: gene = relu(h @ geW2^T + b2), K=128; 4 outputs/warp
    {
        const float4* sh4 = (const float4*)sh;
        float4 hv = sh4[lane];
        const int h = w * 4;
        float a[4];
        #pragma unroll
        for (int u = 0; u < 4; u++)
            a[u] = dot4(((const float4*)(geW2 + (h + u) * H_))[lane], hv);
        wredN<4>(a);
        if (lane == 0) {
            #pragma unroll
            for (int u = 0; u < 4; u++)
                sc[H_ + h + u] = fmaxf(a[u] + geb2[h + u], 0.f);
        }
    }
    __syncthreads();

    // phase 3: g = relu([emb|gene] @ grnW1^T + b1), K=256; 4 outputs/warp
    {
        const float4* sc4 = (const float4*)sc;
        float4 cv0 = sc4[lane], cv1 = sc4[lane + 32];
        const int h = w * 4;
        float a[4];
        #pragma unroll
        for (int u = 0; u < 4; u++) {
            const float4* wp = (const float4*)(grnW1 + (h + u) * 2 * H_);
            a[u] = dot4(wp[lane], cv0) + dot4(wp[lane + 32], cv1);
        }
        wredN<4>(a);
        if (lane == 0) {
            #pragma unroll
            for (int u = 0; u < 4; u++)
                g_buf[b * H_ + h + u] = fmaxf(a[u] + grnb1[h + u], 0.f);
        }
    }
}

// ============================================================================
// K3 (+ folded K2): blocks [0,512) do the big GEMM+epilogue; blocks [512,576)
// compute bx_buf = X @ B2 (grn_b2 viewed [j][i]).
//   C[b,h] = Sum_j X[b,j] * W2[(j*G+i)*H+h]  (128x128x512 bf16 mma)
//   corr[b,i] = Sum_h C[b,h] * g[b,h]        (fused epilogue)
// W2 path: LDG.128 -> registers (1 chunk ahead) -> cvt -> STS bf16.
// No fp32 smem staging. cp.async only for X tiles (depth-3, 4 buffers).
// Exactly ONE __syncthreads per chunk. HBM: W2 read exactly once (134 MB).
// ============================================================================
__device__ __forceinline__ void ldsm_x4(uint32_t addr, uint32_t& r0, uint32_t& r1,
                                        uint32_t& r2, uint32_t& r3) {
    asm volatile("ldmatrix.sync.aligned.m8n8.x4.shared.b16 {%0,%1,%2,%3},[%4];"
                 : "=r"(r0), "=r"(r1), "=r"(r2), "=r"(r3) : "r"(addr));
}
__device__ __forceinline__ void ldsm_x4_t(uint32_t addr, uint32_t& r0, uint32_t& r1,
                                          uint32_t& r2, uint32_t& r3) {
    asm volatile("ldmatrix.sync.aligned.m8n8.x4.trans.shared.b16 {%0,%1,%2,%3},[%4];"
                 : "=r"(r0), "=r"(r1), "=r"(r2), "=r"(r3) : "r"(addr));
}
__device__ __forceinline__ void cp16(void* dst, const void* src) {
    uint32_t d = (uint32_t)__cvta_generic_to_shared(dst);
    asm volatile("cp.async.cg.shared.global [%0],[%1],16;\n" :: "r"(d), "l"(src));
}
#define MMA16816(d, a, b0r, b1r)                                            \
    asm volatile(                                                           \
        "mma.sync.aligned.m16n8k16.row.col.f32.bf16.bf16.f32 "              \
        "{%0,%1,%2,%3},{%4,%5,%6,%7},{%8,%9},{%0,%1,%2,%3};"                \
        : "+f"((d)[0]), "+f"((d)[1]), "+f"((d)[2]), "+f"((d)[3])            \
        : "r"((a)[0]), "r"((a)[1]), "r"((a)[2]), "r"((a)[3]),               \
          "r"(b0r), "r"(b1r))

#define K3_CH   32
#define K3_NCH  16
#define K3_PA   40
#define K3_PB   136
// dynamic smem layout (bytes)
#define K3_SA_OFF   0                       // 4 * 128*40*2  = 40960
#define K3_SB_OFF   40960                   // 2 * 32*136*2  = 17408
#define K3_PRED_OFF 58368                   // 128*8*4       = 4096
#define K3_SMEM     62464

__global__ __launch_bounds__(256, 2) void k3_main(
    const float* __restrict__ W2,
    const float* __restrict__ x,
    const float* __restrict__ b2)
{
    extern __shared__ char smem[];
    const int t = threadIdx.x;

    // ---------------- folded K2: bx_buf = X @ B2 ----------------------------
    if (blockIdx.x >= G_) {
        float* sX = (float*)smem;                                // [16][512]
        float (*sB2)[64] = (float (*)[64])(smem + 16 * G_ * 4);  // [32][64]
        const int blk = blockIdx.x - G_;
        const int bc = blk >> 3, ic = blk & 7;
        const int b0 = bc * 16, i0 = ic * 64;
        const int i_loc = t & 63, bgrp = t >> 6;

        for (int idx = t; idx < 16 * 128; idx += 256) {
            const int r = idx >> 7, c4 = idx & 127;
            ((float4*)(sX + r * G_))[c4] = *(const float4*)(x + (b0 + r) * G_ + c4 * 4);
        }
        float acc[4] = {0.f, 0.f, 0.f, 0.f};
        for (int jc = 0; jc < 16; jc++) {
            __syncthreads();
            for (int idx = t; idx < 32 * 16; idx += 256) {
                const int r = idx >> 4, q = idx & 15;
                ((float4*)sB2[r])[q] = *(const float4*)(b2 + (jc * 32 + r) * G_ + i0 + q * 4);
            }
            __syncthreads();
            #pragma unroll 8
            for (int j = 0; j < 32; j++) {
                const float bv = sB2[j][i_loc];
                #pragma unroll
                for (int r = 0; r < 4; r++)
                    acc[r] += bv * sX[(bgrp * 4 + r) * G_ + jc * 32 + j];
            }
        }
        #pragma unroll
        for (int r = 0; r < 4; r++)
            bx_buf[(b0 + bgrp * 4 + r) * G_ + i0 + i_loc] = acc[r];
        return;
    }

    // ---------------- main GEMM path ----------------------------------------
    __nv_bfloat16* sA = (__nv_bfloat16*)(smem + K3_SA_OFF);  // [4][128*PA]
    __nv_bfloat16* sB = (__nv_bfloat16*)(smem + K3_SB_OFF);  // [2][32*PB]
    float (*pred)[8]  = (float (*)[8])(smem + K3_PRED_OFF);  // [128][8]

    const int i_cta = blockIdx.x;
    const int lane = t & 31, w = t >> 5;
    const int wm = w & 3, wn = w >> 2;
    const int wrow = t >> 3;            // 0..31: W2 row this thread owns
    const int wcol = (t & 7) * 16;      // 16 consecutive floats

    float acc[2][8][4];
    #pragma unroll
    for (int mt = 0; mt < 2; mt++)
        #pragma unroll
        for (int nt = 0; nt < 8; nt++)
            #pragma unroll
            for (int r = 0; r < 4; r++) acc[mt][nt][r] = 0.f;

    // W2 registers: 16 floats = the exact elements this thread converts
    float4 rw0, rw1, rw2, rw3;
    auto ldgW = [&](int c) {
        if (c >= K3_NCH) return;
        const float4* gsrc = (const float4*)(W2 +
            ((long)(c * K3_CH + wrow) * G_ + i_cta) * H_ + wcol);
        rw0 = __ldg(gsrc);
        rw1 = __ldg(gsrc + 1);
        rw2 = __ldg(gsrc + 2);
        rw3 = __ldg(gsrc + 3);
    };

    auto issueA = [&](int c) {
        if (c >= K3_NCH) return;
        __nv_bfloat16* sAb = sA + (c & 3) * 128 * K3_PA;
        const int j0 = c * K3_CH;
        #pragma unroll
        for (int k = 0; k < 2; k++) {
            const int idx = t + k * 256;
            const int r = idx >> 2, q = idx & 3;
            cp16(&sAb[r * K3_PA + q * 8], &xbf_buf[r * G_ + j0 + q * 8]);
        }
        asm volatile("cp.async.commit_group;\n" ::: "memory");
    };

    ldgW(0);
    issueA(0); issueA(1); issueA(2);
    for (int c = 0; c < K3_NCH; c++) {
        // convert OWN registers (chunk c) -> bf16 STS. sB[c&1] last read by
        // MMA(c-2), finished by every warp before the iter-(c-1) barrier.
        {
            __nv_bfloat16* sBb = sB + (c & 1) * K3_CH * K3_PB;
            __nv_bfloat162 p0 = __floats2bfloat162_rn(rw0.x, rw0.y);
            __nv_bfloat162 p1 = __floats2bfloat162_rn(rw0.z, rw0.w);
            __nv_bfloat162 p2 = __floats2bfloat162_rn(rw1.x, rw1.y);
            __nv_bfloat162 p3 = __floats2bfloat162_rn(rw1.z, rw1.w);
            __nv_bfloat162 p4 = __floats2bfloat162_rn(rw2.x, rw2.y);
            __nv_bfloat162 p5 = __floats2bfloat162_rn(rw2.z, rw2.w);
            __nv_bfloat162 p6 = __floats2bfloat162_rn(rw3.x, rw3.y);
            __nv_bfloat162 p7 = __floats2bfloat162_rn(rw3.z, rw3.w);
            uint4 o0, o1;
            o0.x = *(uint32_t*)&p0; o0.y = *(uint32_t*)&p1;
            o0.z = *(uint32_t*)&p2; o0.w = *(uint32_t*)&p3;
            o1.x = *(uint32_t*)&p4; o1.y = *(uint32_t*)&p5;
            o1.z = *(uint32_t*)&p6; o1.w = *(uint32_t*)&p7;
            *(uint4*)&sBb[wrow * K3_PB + wcol]     = o0;
            *(uint4*)&sBb[wrow * K3_PB + wcol + 8] = o1;
        }
        // prefetch next chunk's W2 into registers (consumed next iteration)
        ldgW(c + 1);

        if (c < K3_NCH - 2)
            asm volatile("cp.async.wait_group 2;\n" ::: "memory");
        else if (c == K3_NCH - 2)
            asm volatile("cp.async.wait_group 1;\n" ::: "memory");
        else
            asm volatile("cp.async.wait_group 0;\n" ::: "memory");
        __syncthreads();   // sole barrier: STS + cp.async(c) visible to all

        const __nv_bfloat16* sAc = sA + (c & 3) * 128 * K3_PA;
        const __nv_bfloat16* sBc = sB + (c & 1) * K3_CH * K3_PB;
        #pragma unroll
        for (int ks = 0; ks < K3_CH; ks += 16) {
            uint32_t afr[2][4];
            #pragma unroll
            for (int mt = 0; mt < 2; mt++) {
                const int row = wm * 32 + mt * 16 + (lane & 15);
                const int col = ks + ((lane >> 4) << 3);
                uint32_t a = (uint32_t)__cvta_generic_to_shared(&sAc[row * K3_PA + col]);
                ldsm_x4(a, afr[mt][0], afr[mt][1], afr[mt][2], afr[mt][3]);
            }
            uint32_t bfr[4][4];
            #pragma unroll
            for (int n4 = 0; n4 < 4; n4++) {
                const int krow = ks + (lane & 15);
                const int col = wn * 64 + n4 * 16 + ((lane >> 4) << 3);
                uint32_t a = (uint32_t)__cvta_generic_to_shared(&sBc[krow * K3_PB + col]);
                ldsm_x4_t(a, bfr[n4][0], bfr[n4][1], bfr[n4][2], bfr[n4][3]);
            }
            #pragma unroll
            for (int mt = 0; mt < 2; mt++)
                #pragma unroll
                for (int nt = 0; nt < 8; nt++) {
                    const int n4 = nt >> 1, p = (nt & 1) * 2;
                    MMA16816(acc[mt][nt], afr[mt], bfr[n4][p], bfr[n4][p + 1]);
                }
        }
        issueA(c + 3);     // sA[(c+3)&3] last read in MMA(c-1): done by all
    }

    // epilogue: corr[b,i_cta] = Sum_h C[b,h]*g[b,h] (deterministic)
    const int rg = lane >> 2, tig = lane & 3;
    #pragma unroll
    for (int mt = 0; mt < 2; mt++) {
        float p0 = 0.f, p1 = 0.f;
        const int brow = wm * 32 + mt * 16 + rg;
        #pragma unroll
        for (int nt = 0; nt < 8; nt++) {
            const int h0 = wn * 64 + nt * 8 + tig * 2;
            float g0 = __ldg(&g_buf[brow * H_ + h0]);
            float g1 = __ldg(&g_buf[brow * H_ + h0 + 1]);
            float g2 = __ldg(&g_buf[(brow + 8) * H_ + h0]);
            float g3 = __ldg(&g_buf[(brow + 8) * H_ + h0 + 1]);
            p0 += acc[mt][nt][0] * g0 + acc[mt][nt][1] * g1;
            p1 += acc[mt][nt][2] * g2 + acc[mt][nt][3] * g3;
        }
        pred[brow][wn * 4 + tig]     = p0;
        pred[brow + 8][wn * 4 + tig] = p1;
    }
    __syncthreads();
    if (t < 128) {
        float s = 0.f;
        #pragma unroll
        for (int cc = 0; cc < 8; cc++) s += pred[t][cc];
        corr_buf[t * G_ + i_cta] = s;     // [b][i] layout
    }
}

// ============================================================================
// K4: y = x/c + (alpha/2)*(corr + Bx)/c^2 ; decoder ; residual. CTA per b.
// 1024 threads (32 warps): 4 (then 16) outputs per warp.
// ============================================================================
__global__ __launch_bounds__(1024) void k4_dec(
    const float* __restrict__ x,
    const float* __restrict__ dW1, const float* __restrict__ db1,
    const float* __restrict__ dW2, const float* __restrict__ db2,
    float* __restrict__ out)
{
    __shared__ __align__(16) float sx[G_];
    __shared__ __align__(16) float sy[G_];
    __shared__ __align__(16) float sd[H_];
    const int b = blockIdx.x, t = threadIdx.x;
    const int lane = t & 31, w = t >> 5;
    const float cinv = 1.0f / (1.0f + 1e-6f);
    const float scale = kAlphaHalf * cinv * cinv;

    if (t < G_) {
        const float xv = x[b * G_ + t];
        sx[t] = xv;
        const float corr = corr_buf[b * G_ + t] + bx_buf[b * G_ + t];
        sy[t] = xv * cinv + corr * scale;
    }
    __syncthreads();

    // d = relu(y @ dW1^T + b1), K=512; 4 outputs/warp
    {
        const float4* sy4 = (const float4*)sy;
        float4 yv[4];
        #pragma unroll
        for (int k = 0; k < 4; k++) yv[k] = sy4[lane + 32 * k];
        const int h = w * 4;
        float a[4];
        #pragma unroll
        for (int u = 0; u < 4; u++) {
            const float4* wp = (const float4*)(dW1 + (h + u) * G_);
            float s = 0.f;
            #pragma unroll
            for (int k = 0; k < 4; k++) s += dot4(wp[lane + 32 * k], yv[k]);
            a[u] = s;
        }
        wredN<4>(a);
        if (lane == 0) {
            #pragma unroll
            for (int u = 0; u < 4; u++)
                sd[h + u] = fmaxf(a[u] + db1[h + u], 0.f);
        }
    }
    __syncthreads();

    // out = x + d @ dW2^T + b2, K=128; 16 outputs/warp (2 groups of U=8)
    {
        const float4* sd4 = (const float4*)sd;
        float4 dv = sd4[lane];
        #pragma unroll
        for (int og = 0; og < 2; og++) {
            const int i = w * 16 + og * 8;
            float a[8];
            #pragma unroll
            for (int u = 0; u < 8; u++)
                a[u] = dot4(((const float4*)(dW2 + (i + u) * H_))[lane], dv);
            wredN<8>(a);
            if (lane == 0) {
                #pragma unroll
                for (int u = 0; u < 8; u++)
                    out[b * G_ + i + u] = sx[i + u] + db2[i + u] + a[u];
            }
        }
    }
}

// ============================================================================
extern "C" void kernel_launch(void* const* d_in, const int* in_sizes, int n_in,
                              void* d_out, int out_size)
{
    (void)in_sizes; (void)n_in; (void)out_size;
    const int*   pert  = (const int*)  d_in[0];
    const float* x     = (const float*)d_in[1];
    const float* embW  = (const float*)d_in[2];
    const float* geW1  = (const float*)d_in[3];
    const float* geb1  = (const float*)d_in[4];
    const float* geW2  = (const float*)d_in[5];
    const float* geb2  = (const float*)d_in[6];
    const float* grnW1 = (const float*)d_in[7];
    const float* grnb1 = (const float*)d_in[8];
    const float* grnW2 = (const float*)d_in[9];
    const float* grnb2 = (const float*)d_in[10];
    const float* dW1   = (const float*)d_in[11];
    const float* db1   = (const float*)d_in[12];
    const float* dW2   = (const float*)d_in[13];
    const float* db2   = (const float*)d_in[14];
    float* out = (float*)d_out;

    cudaFuncSetAttribute(k3_main, cudaFuncAttributeMaxDynamicSharedMemorySize,
                         K3_SMEM);

    k1_encode<<<B_, 1024>>>(pert, x, embW, geW1, geb1, geW2, geb2, grnW1, grnb1);
    k3_main<<<G_ + 64, 256, K3_SMEM>>>(grnW2, x, grnb2);
    k4_dec<<<B_, 1024>>>(x, dW1, db1, dW2, db2, out);
}